// round 13
// baseline (speedup 1.0000x reference)
#include <cuda_runtime.h>
#include <cstdint>

#define B_SZ   32
#define N_E    500000
#define N_T    2000000
#define N_R    200
#define N_W2V  300

// Subj-sort binning: 128 entities per bin -> 16 KB src window per bin.
#define BIN_SHIFT 7
#define NBINS     3907          // ceil(500000 / 128)
#define BINS_PER_THR 16         // 256 threads * 16 = 4096 >= NBINS

// Entity-major buffers [N_E][32]; buf0 = T(x), buf_k = result after hop k.
__device__ float g_buf0[(size_t)N_E * B_SZ];
__device__ float g_buf1[(size_t)N_E * B_SZ];
__device__ float g_buf2[(size_t)N_E * B_SZ];
__device__ float g_buf3[(size_t)N_E * B_SZ];
__device__ float g_rt[3 * N_R * B_SZ];

// Binning state (zero-init at load; re-zeroed in epilogue each call).
__device__ int g_hist[NBINS];
__device__ int g_pos[NBINS];
// Triples sorted by subj-bin (order reused by all 3 hops).
__device__ int g_ss[N_T];
__device__ int g_rr[N_T];
__device__ int g_oo[N_T];

#define ZERO_BLOCKS 15625    // 4M float4 / 256
#define HIST_CHUNK  7813     // triples per histogram/scatter block (256 blocks)

// ---------------------------------------------------------------------------
// Fused prologue, one launch, 256-thread blocks, dispatch on blockIdx.x:
//   [0, 300)       : rmlp (serial-latency work first — wave 0)
//   [300, 556)     : subj-bin histogram -> g_hist (smem-aggregated)
//   [556, +15625)  : zero buf1
//   [.., +15625)   : transpose x [32,N_E] -> buf0 [N_E,32]
// ---------------------------------------------------------------------------
#define PRE_RMLP_BLOCKS 300
#define PRE_HIST_BLOCKS 256
#define PRE_TIN_BLOCKS  15625
#define PRE_TOTAL_BLOCKS (PRE_RMLP_BLOCKS + PRE_HIST_BLOCKS + ZERO_BLOCKS + PRE_TIN_BLOCKS)

__global__ void __launch_bounds__(256)
fused_pre_kernel(const float* __restrict__ x, const float* __restrict__ q,
                 const int* __restrict__ subj,
                 const float* __restrict__ W1, const float* __restrict__ b1,
                 const float* __restrict__ W2, const float* __restrict__ b2,
                 const float* __restrict__ W3, const float* __restrict__ b3,
                 float* __restrict__ buf0, float4* __restrict__ z1,
                 float* __restrict__ rt) {
    int bid = blockIdx.x;
    int tid = threadIdx.x;

    if (bid < PRE_RMLP_BLOCKS) {
        // ---- rmlp: 2 (hop,rel) tasks per block, 4 warps per task ----
        __shared__ float partial[2][4][32];
        int task   = tid >> 7;
        int wg_tid = tid & 127;
        int wip    = wg_tid >> 5;
        int lane   = tid & 31;
        int gt     = bid * 2 + task;
        int hop    = gt / N_R;
        int rel_i  = gt - hop * N_R;

        const float* W = (hop == 0) ? W1 : (hop == 1) ? W2 : W3;
        const float* b = (hop == 0) ? b1 : (hop == 1) ? b2 : b3;

        int k0 = wip * 75;
        const float* qrow = q + (size_t)lane * N_W2V;
        float a0 = 0.f, a1 = 0.f, a2 = 0.f;
#pragma unroll
        for (int k = 0; k < 75; k += 3) {
            a0 = fmaf(qrow[k0 + k + 0], __ldg(W + (size_t)(k0 + k + 0) * N_R + rel_i), a0);
            a1 = fmaf(qrow[k0 + k + 1], __ldg(W + (size_t)(k0 + k + 1) * N_R + rel_i), a1);
            a2 = fmaf(qrow[k0 + k + 2], __ldg(W + (size_t)(k0 + k + 2) * N_R + rel_i), a2);
        }
        partial[task][wip][lane] = a0 + a1 + a2;
        __syncthreads();

        if (wg_tid < 32) {
            float acc = b[rel_i] + partial[task][0][lane] + partial[task][1][lane]
                      + partial[task][2][lane] + partial[task][3][lane];
            rt[((size_t)hop * N_R + rel_i) * B_SZ + lane] = acc;
        }
        return;
    }

    if (bid < PRE_RMLP_BLOCKS + PRE_HIST_BLOCKS) {
        // ---- subj-bin histogram (smem aggregate, then flush) ----
        __shared__ int hcnt[NBINS];
        for (int i = tid; i < NBINS; i += 256) hcnt[i] = 0;
        __syncthreads();
        int base = (bid - PRE_RMLP_BLOCKS) * HIST_CHUNK;
        for (int i = tid; i < HIST_CHUNK; i += 256) {
            int t = base + i;
            if (t < N_T) atomicAdd(&hcnt[__ldg(subj + t) >> BIN_SHIFT], 1);
        }
        __syncthreads();
        for (int i = tid; i < NBINS; i += 256) {
            int c = hcnt[i];
            if (c) atomicAdd(&g_hist[i], c);
        }
        return;
    }

    if (bid < PRE_RMLP_BLOCKS + PRE_HIST_BLOCKS + ZERO_BLOCKS) {
        size_t i = (size_t)(bid - PRE_RMLP_BLOCKS - PRE_HIST_BLOCKS) * 256 + tid;
        z1[i] = make_float4(0.f, 0.f, 0.f, 0.f);
        return;
    }

    // ---- transpose-in: 32 entities per block ----
    {
        __shared__ float tile[32][33];
        int e0 = (bid - PRE_RMLP_BLOCKS - PRE_HIST_BLOCKS - ZERO_BLOCKS) * 32;
        int tx = tid & 31;
        int row = tid >> 5;
#pragma unroll
        for (int p = 0; p < 4; p++) {
            int b = row + p * 8;
            tile[b][tx] = x[(size_t)b * N_E + e0 + tx];
        }
        __syncthreads();
#pragma unroll
        for (int p = 0; p < 4; p++) {
            int j = row + p * 8;
            buf0[(size_t)(e0 + j) * 32 + tx] = tile[tx][j];
        }
    }
}

// ---------------------------------------------------------------------------
// Counting-sort scatter: triples -> (g_ss, g_rr, g_oo) ordered by subj bin.
// 256 blocks. Each block: (1) computes the global exclusive prefix of g_hist
// (redundantly, smem), (2) counts its chunk per bin, (3) reserves per-bin
// space via g_pos, (4) places with smem rank cursors.
// ---------------------------------------------------------------------------
__global__ void __launch_bounds__(256)
scatter_kernel(const int* __restrict__ subj, const int* __restrict__ rel,
               const int* __restrict__ obj) {
    __shared__ int hoff[NBINS];      // exclusive prefix -> reserved block base
    __shared__ int cnt[NBINS];
    __shared__ int partial[256];

    int bid = blockIdx.x;
    int tid = threadIdx.x;

    // per-thread serial scan over its 16 bins
    int base_b = tid * BINS_PER_THR;
    int local[BINS_PER_THR];
    int sum = 0;
#pragma unroll
    for (int k = 0; k < BINS_PER_THR; k++) {
        int b = base_b + k;
        int v = (b < NBINS) ? g_hist[b] : 0;
        local[k] = sum;
        sum += v;
    }
    partial[tid] = sum;
    __syncthreads();
    if (tid == 0) {
        int acc = 0;
        for (int i = 0; i < 256; i++) { int v = partial[i]; partial[i] = acc; acc += v; }
    }
    __syncthreads();
#pragma unroll
    for (int k = 0; k < BINS_PER_THR; k++) {
        int b = base_b + k;
        if (b < NBINS) hoff[b] = partial[tid] + local[k];
    }
    for (int i = tid; i < NBINS; i += 256) cnt[i] = 0;
    __syncthreads();

    int base = bid * HIST_CHUNK;

    // local counts for this chunk
    for (int i = tid; i < HIST_CHUNK; i += 256) {
        int t = base + i;
        if (t < N_T) atomicAdd(&cnt[__ldg(subj + t) >> BIN_SHIFT], 1);
    }
    __syncthreads();

    // reserve per-bin space; hoff becomes this block's write base
    for (int b = tid; b < NBINS; b += 256) {
        int c = cnt[b];
        if (c) hoff[b] += atomicAdd(&g_pos[b], c);
        cnt[b] = 0;
    }
    __syncthreads();

    // place
    for (int i = tid; i < HIST_CHUNK; i += 256) {
        int t = base + i;
        if (t < N_T) {
            int s = __ldg(subj + t);
            int b = s >> BIN_SHIFT;
            int r = atomicAdd(&cnt[b], 1);
            int pos = hoff[b] + r;
            g_ss[pos] = s;
            g_rr[pos] = __ldg(rel + t);
            g_oo[pos] = __ldg(obj + t);
        }
    }
}

// ---------------------------------------------------------------------------
// Epilogue: transpose selected buffer [N_E,32] -> out [32,N_E]; spare blocks
// reset g_hist / g_pos for the next call.
// ---------------------------------------------------------------------------
#define TOUT_BLOCKS 15625
#define RESET_BLOCKS 4      // 4 * 1024 = 4096 >= NBINS

__global__ void transpose_out_kernel(const float* __restrict__ b0,
                                     const float* __restrict__ b1,
                                     const float* __restrict__ b2,
                                     const float* __restrict__ b3,
                                     const int* __restrict__ n_hop,
                                     float* __restrict__ out) {
    int bid = blockIdx.x;
    int tx = threadIdx.x, ty = threadIdx.y;

    if (bid >= TOUT_BLOCKS) {
        int idx = (bid - TOUT_BLOCKS) * 1024 + ty * 32 + tx;
        if (idx < NBINS) { g_hist[idx] = 0; g_pos[idx] = 0; }
        return;
    }

    __shared__ float tile[32][33];
    int nh = *n_hop;
    nh = nh < 0 ? 0 : (nh > 3 ? 3 : nh);
    const float* wt = (nh == 0) ? b0 : (nh == 1) ? b1 : (nh == 2) ? b2 : b3;

    int e0 = bid * 32;
    tile[ty][tx] = wt[(size_t)(e0 + ty) * 32 + tx];
    __syncthreads();
    out[(size_t)ty * N_E + e0 + tx] = tile[tx][ty];
}

// ---------------------------------------------------------------------------
// One hop over the SUBJ-SORTED triple stream: octet of 8 lanes handles TPO=4
// consecutive triples; per lane one float4 (4 of 32 batches).
// src gathers are clustered in a 16 KB window -> L1 hits (LTS bytes cut ~3x).
// dst REDs stay randomly spread -> no same-address atomic serialization.
// Trailing ZERO_BLOCKS zero the NEXT hop's destination (overlapped).
// ---------------------------------------------------------------------------
#define TPO 4
#define HOP_BLOCKS 15625   // N_T * 8 / TPO / 256

__global__ void __launch_bounds__(256, 8)
hop_kernel(const float* __restrict__ src, float* __restrict__ dst,
           const float* __restrict__ rt,
           const int* __restrict__ n_hop, int hop,
           float4* __restrict__ zbuf) {
    if (*n_hop < hop) return;

    int bid = blockIdx.x;
    int tid = threadIdx.x;

    if (bid >= HOP_BLOCKS) {
        size_t i = (size_t)(bid - HOP_BLOCKS) * 256 + tid;
        zbuf[i] = make_float4(0.f, 0.f, 0.f, 0.f);
        return;
    }

    int lane = tid & 31;
    int sub  = lane & 7;
    int oct  = (int)(((size_t)bid * 256 + tid) >> 3);
    int t0   = oct * TPO;
    if (t0 >= N_T) return;

    int4 sA = __ldg(reinterpret_cast<const int4*>(g_ss + t0));
    int4 rA = __ldg(reinterpret_cast<const int4*>(g_rr + t0));
    int4 oA = __ldg(reinterpret_cast<const int4*>(g_oo + t0));

    int s[TPO]  = {sA.x, sA.y, sA.z, sA.w};
    int rl[TPO] = {rA.x, rA.y, rA.z, rA.w};
    int o[TPO]  = {oA.x, oA.y, oA.z, oA.w};

    const float4* src4 = reinterpret_cast<const float4*>(src);
    const float4* rt4  = reinterpret_cast<const float4*>(rt);
    float4* dst4       = reinterpret_cast<float4*>(dst);

    // front-batch gathers (clustered subj -> L1-resident window)
    float4 a[TPO];
#pragma unroll
    for (int j = 0; j < TPO; j++) a[j] = __ldg(src4 + (size_t)s[j] * 8 + sub);

    float4 r4[TPO];
#pragma unroll
    for (int j = 0; j < TPO; j++) r4[j] = __ldg(rt4 + (size_t)rl[j] * 8 + sub);

#pragma unroll
    for (int j = 0; j < TPO; j++) {
        float4 m = make_float4(a[j].x * r4[j].x, a[j].y * r4[j].y,
                               a[j].z * r4[j].z, a[j].w * r4[j].w);
        float4* d = dst4 + (size_t)o[j] * 8 + sub;
        asm volatile("red.global.add.v4.f32 [%0], {%1, %2, %3, %4};"
                     :: "l"(d), "f"(m.x), "f"(m.y), "f"(m.z), "f"(m.w)
                     : "memory");
    }
}

// ---------------------------------------------------------------------------
// kernel_launch
// Input order (metadata): x, q, subj_idx, rel_idx, obj_idx, W1, b1, W2, b2, W3, b3, n_hop
// ---------------------------------------------------------------------------
extern "C" void kernel_launch(void* const* d_in, const int* in_sizes, int n_in,
                              void* d_out, int out_size) {
    const float* x     = (const float*)d_in[0];
    const float* q     = (const float*)d_in[1];
    const int* subj    = (const int*)d_in[2];
    const int* rel     = (const int*)d_in[3];
    const int* obj     = (const int*)d_in[4];
    const float* W1    = (const float*)d_in[5];
    const float* b1    = (const float*)d_in[6];
    const float* W2    = (const float*)d_in[7];
    const float* b2    = (const float*)d_in[8];
    const float* W3    = (const float*)d_in[9];
    const float* b3    = (const float*)d_in[10];
    const int* n_hop   = (const int*)d_in[11];
    float* out         = (float*)d_out;

    float *buf0, *buf1, *buf2, *buf3, *rt;
    cudaGetSymbolAddress((void**)&buf0, g_buf0);
    cudaGetSymbolAddress((void**)&buf1, g_buf1);
    cudaGetSymbolAddress((void**)&buf2, g_buf2);
    cudaGetSymbolAddress((void**)&buf3, g_buf3);
    cudaGetSymbolAddress((void**)&rt, g_rt);

    // prologue: rmlp + subj histogram + zero buf1 + transpose-in, one launch
    fused_pre_kernel<<<PRE_TOTAL_BLOCKS, 256>>>(
        x, q, subj, W1, b1, W2, b2, W3, b3, buf0, (float4*)buf1, rt);

    // subj-bin counting sort (order reused by all hops)
    scatter_kernel<<<PRE_HIST_BLOCKS, 256>>>(subj, rel, obj);

    // hops on the sorted stream; hop1 zeroes buf2, hop2 zeroes buf3
    hop_kernel<<<HOP_BLOCKS + ZERO_BLOCKS, 256>>>(
        buf0, buf1, rt + 0 * N_R * B_SZ, n_hop, 1, (float4*)buf2);
    hop_kernel<<<HOP_BLOCKS + ZERO_BLOCKS, 256>>>(
        buf1, buf2, rt + 1 * N_R * B_SZ, n_hop, 2, (float4*)buf3);
    hop_kernel<<<HOP_BLOCKS, 256>>>(
        buf2, buf3, rt + 2 * N_R * B_SZ, n_hop, 3, nullptr);

    // epilogue: transpose selected buffer to [B, N_E] + reset bin state
    transpose_out_kernel<<<TOUT_BLOCKS + RESET_BLOCKS, dim3(32, 32)>>>(
        buf0, buf1, buf2, buf3, n_hop, out);
}

// round 14
// speedup vs baseline: 1.6152x; 1.6152x over previous
#include <cuda_runtime.h>
#include <cstdint>

#define B_SZ   32
#define N_E    500000
#define N_T    2000000
#define N_R    200
#define N_W2V  300

// Scratch: entity-major buffers [N_E][32] (buf0 = T(x), buf_k = result after hop k)
// and r activations [3][N_R][32]
__device__ float g_buf0[(size_t)N_E * B_SZ];
__device__ float g_buf1[(size_t)N_E * B_SZ];
__device__ float g_buf2[(size_t)N_E * B_SZ];
__device__ float g_buf3[(size_t)N_E * B_SZ];
__device__ float g_rt[3 * N_R * B_SZ];

#define ZERO_BLOCKS 15625   // 4M float4 / 256 threads

// ---------------------------------------------------------------------------
// Fused prologue, one launch, 256-thread blocks, dispatch on blockIdx.x:
//   [0, 300)           : rmlp — 2 (hop,rel) tasks per block, 4 warps per task
//                        (k-loop split 75/warp, smem-reduced). FIRST so the
//                        serial-latency work starts in wave 0, not the tail.
//   [300, 300+15625)   : zero buf1 (hop1's destination)
//   [.., +15625)       : transpose x [32,N_E] -> buf0 [N_E,32]
// Sections touch disjoint memory; no intra-launch ordering needed.
// ---------------------------------------------------------------------------
#define PRE_RMLP_BLOCKS 300     // 600 tasks / 2 per block
#define PRE_TIN_BLOCKS  15625
#define PRE_TOTAL_BLOCKS (PRE_RMLP_BLOCKS + ZERO_BLOCKS + PRE_TIN_BLOCKS)

__global__ void __launch_bounds__(256)
fused_pre_kernel(const float* __restrict__ x, const float* __restrict__ q,
                 const float* __restrict__ W1, const float* __restrict__ b1,
                 const float* __restrict__ W2, const float* __restrict__ b2,
                 const float* __restrict__ W3, const float* __restrict__ b3,
                 float* __restrict__ buf0, float4* __restrict__ z1,
                 float* __restrict__ rt) {
    int bid = blockIdx.x;
    int tid = threadIdx.x;

    if (bid < PRE_RMLP_BLOCKS) {
        // ---- rmlp section ----
        __shared__ float partial[2][4][32];
        int task   = tid >> 7;            // 0..1 within block
        int wg_tid = tid & 127;
        int wip    = wg_tid >> 5;         // warp in task: 0..3
        int lane   = tid & 31;            // batch
        int gt     = bid * 2 + task;      // global (hop,rel) task: 0..599
        int hop    = gt / N_R;
        int rel    = gt - hop * N_R;

        const float* W = (hop == 0) ? W1 : (hop == 1) ? W2 : W3;
        const float* b = (hop == 0) ? b1 : (hop == 1) ? b2 : b3;

        // each warp covers k in [wip*75, wip*75+75)
        int k0 = wip * 75;
        const float* qrow = q + (size_t)lane * N_W2V;
        float a0 = 0.f, a1 = 0.f, a2 = 0.f;
#pragma unroll
        for (int k = 0; k < 75; k += 3) {
            a0 = fmaf(qrow[k0 + k + 0], __ldg(W + (size_t)(k0 + k + 0) * N_R + rel), a0);
            a1 = fmaf(qrow[k0 + k + 1], __ldg(W + (size_t)(k0 + k + 1) * N_R + rel), a1);
            a2 = fmaf(qrow[k0 + k + 2], __ldg(W + (size_t)(k0 + k + 2) * N_R + rel), a2);
        }
        partial[task][wip][lane] = a0 + a1 + a2;
        __syncthreads();

        if (wg_tid < 32) {
            float acc = b[rel] + partial[task][0][lane] + partial[task][1][lane]
                      + partial[task][2][lane] + partial[task][3][lane];
            rt[((size_t)hop * N_R + rel) * B_SZ + lane] = acc;
        }
        return;
    }

    if (bid < PRE_RMLP_BLOCKS + ZERO_BLOCKS) {
        size_t i = (size_t)(bid - PRE_RMLP_BLOCKS) * 256 + tid;
        z1[i] = make_float4(0.f, 0.f, 0.f, 0.f);
        return;
    }

    // ---- transpose-in section: 32 entities per block ----
    {
        __shared__ float tile[32][33];
        int e0 = (bid - PRE_RMLP_BLOCKS - ZERO_BLOCKS) * 32;
        int tx = tid & 31;
        int row = tid >> 5;       // 0..7
#pragma unroll
        for (int p = 0; p < 4; p++) {
            int b = row + p * 8;
            tile[b][tx] = x[(size_t)b * N_E + e0 + tx];
        }
        __syncthreads();
#pragma unroll
        for (int p = 0; p < 4; p++) {
            int j = row + p * 8;
            buf0[(size_t)(e0 + j) * 32 + tx] = tile[tx][j];
        }
    }
}

// ---------------------------------------------------------------------------
// Transpose selected buffer [N_E, 32] -> out [32, N_E].
// Source buffer chosen device-side from *n_hop (0..3).
// ---------------------------------------------------------------------------
__global__ void transpose_out_kernel(const float* __restrict__ b0,
                                     const float* __restrict__ b1,
                                     const float* __restrict__ b2,
                                     const float* __restrict__ b3,
                                     const int* __restrict__ n_hop,
                                     float* __restrict__ out) {
    __shared__ float tile[32][33];
    int nh = *n_hop;
    nh = nh < 0 ? 0 : (nh > 3 ? 3 : nh);
    const float* wt = (nh == 0) ? b0 : (nh == 1) ? b1 : (nh == 2) ? b2 : b3;

    int e0 = blockIdx.x * 32;
    int tx = threadIdx.x, ty = threadIdx.y;
    tile[ty][tx] = wt[(size_t)(e0 + ty) * 32 + tx];
    __syncthreads();
    out[(size_t)ty * N_E + e0 + tx] = tile[tx][ty];
}

// ---------------------------------------------------------------------------
// One hop: for each triple t:  dst[:, obj[t]] += src[:, subj[t]] * r[:, rel[t]]
// Entity-major layout: src/dst are [N_E][32]. Each octet of 8 lanes handles
// TPO=4 consecutive triples (ORIGINAL random order — measured best for both
// the gather and the RED streams); per lane one float4 (4 of the 32 batches).
// Trailing ZERO_BLOCKS (when zbuf != null) zero the NEXT hop's destination,
// overlapping that streaming write with this hop's REDG-bound atomics.
// NOTE: plain launch_bounds — the (256, 8) occupancy clamp measured SLOWER
// (61.3 vs 57.5 us; cross-CTA L1tex-queue contention at high occ).
// ---------------------------------------------------------------------------
#define TPO 4   // triples per octet
#define HOP_BLOCKS 15625   // N_T * 8 / TPO / 256

__global__ void __launch_bounds__(256)
hop_kernel(const float* __restrict__ src, float* __restrict__ dst,
           const int* __restrict__ subj, const int* __restrict__ rel,
           const int* __restrict__ obj, const float* __restrict__ rt,
           const int* __restrict__ n_hop, int hop,
           float4* __restrict__ zbuf) {
    if (*n_hop < hop) return;

    int bid = blockIdx.x;
    int tid = threadIdx.x;

    if (bid >= HOP_BLOCKS) {
        // ---- zero next hop's destination (disjoint from dst) ----
        size_t i = (size_t)(bid - HOP_BLOCKS) * 256 + tid;
        zbuf[i] = make_float4(0.f, 0.f, 0.f, 0.f);
        return;
    }

    int lane = tid & 31;
    int sub  = lane & 7;                                    // which float4 of 32 batches
    int oct  = (int)(((size_t)bid * 256 + tid) >> 3);       // octet id
    int t0   = oct * TPO;
    if (t0 >= N_T) return;

    // 4 triples' indices via one int4 load per array (t0 % 4 == 0)
    int4 sA = __ldg(reinterpret_cast<const int4*>(subj + t0));
    int4 rA = __ldg(reinterpret_cast<const int4*>(rel + t0));
    int4 oA = __ldg(reinterpret_cast<const int4*>(obj + t0));

    int s[TPO]  = {sA.x, sA.y, sA.z, sA.w};
    int rl[TPO] = {rA.x, rA.y, rA.z, rA.w};
    int o[TPO]  = {oA.x, oA.y, oA.z, oA.w};

    const float4* src4 = reinterpret_cast<const float4*>(src);
    const float4* rt4  = reinterpret_cast<const float4*>(rt);
    float4* dst4       = reinterpret_cast<float4*>(dst);

    // front-batch all long-latency gathers
    float4 a[TPO];
#pragma unroll
    for (int j = 0; j < TPO; j++) a[j] = __ldg(src4 + (size_t)s[j] * 8 + sub);

    // r-vector loads are hot in L1 (25.6 KB table)
    float4 r4[TPO];
#pragma unroll
    for (int j = 0; j < TPO; j++) r4[j] = __ldg(rt4 + (size_t)rl[j] * 8 + sub);

#pragma unroll
    for (int j = 0; j < TPO; j++) {
        float4 m = make_float4(a[j].x * r4[j].x, a[j].y * r4[j].y,
                               a[j].z * r4[j].z, a[j].w * r4[j].w);
        float4* d = dst4 + (size_t)o[j] * 8 + sub;
        asm volatile("red.global.add.v4.f32 [%0], {%1, %2, %3, %4};"
                     :: "l"(d), "f"(m.x), "f"(m.y), "f"(m.z), "f"(m.w)
                     : "memory");
    }
}

// ---------------------------------------------------------------------------
// kernel_launch
// Input order (metadata): x, q, subj_idx, rel_idx, obj_idx, W1, b1, W2, b2, W3, b3, n_hop
// ---------------------------------------------------------------------------
extern "C" void kernel_launch(void* const* d_in, const int* in_sizes, int n_in,
                              void* d_out, int out_size) {
    const float* x     = (const float*)d_in[0];
    const float* q     = (const float*)d_in[1];
    const int* subj    = (const int*)d_in[2];
    const int* rel     = (const int*)d_in[3];
    const int* obj     = (const int*)d_in[4];
    const float* W1    = (const float*)d_in[5];
    const float* b1    = (const float*)d_in[6];
    const float* W2    = (const float*)d_in[7];
    const float* b2    = (const float*)d_in[8];
    const float* W3    = (const float*)d_in[9];
    const float* b3    = (const float*)d_in[10];
    const int* n_hop   = (const int*)d_in[11];
    float* out         = (float*)d_out;

    float *buf0, *buf1, *buf2, *buf3, *rt;
    cudaGetSymbolAddress((void**)&buf0, g_buf0);
    cudaGetSymbolAddress((void**)&buf1, g_buf1);
    cudaGetSymbolAddress((void**)&buf2, g_buf2);
    cudaGetSymbolAddress((void**)&buf3, g_buf3);
    cudaGetSymbolAddress((void**)&rt, g_rt);

    // prologue: rmlp (first) + zero buf1 + transpose-in, one launch
    fused_pre_kernel<<<PRE_TOTAL_BLOCKS, 256>>>(
        x, q, W1, b1, W2, b2, W3, b3, buf0, (float4*)buf1, rt);

    // hop1 zeroes buf2 alongside; hop2 zeroes buf3; hop3 has no zero section
    hop_kernel<<<HOP_BLOCKS + ZERO_BLOCKS, 256>>>(
        buf0, buf1, subj, rel, obj, rt + 0 * N_R * B_SZ, n_hop, 1, (float4*)buf2);
    hop_kernel<<<HOP_BLOCKS + ZERO_BLOCKS, 256>>>(
        buf1, buf2, subj, rel, obj, rt + 1 * N_R * B_SZ, n_hop, 2, (float4*)buf3);
    hop_kernel<<<HOP_BLOCKS, 256>>>(
        buf2, buf3, subj, rel, obj, rt + 2 * N_R * B_SZ, n_hop, 3, nullptr);

    // back to [B, N_E], selecting the buffer that matches n_hop
    transpose_out_kernel<<<N_E / 32, dim3(32, 32)>>>(buf0, buf1, buf2, buf3, n_hop, out);
}